// round 16
// baseline (speedup 1.0000x reference)
#include <cuda_runtime.h>
#include <cstdint>

// ============================================================================
// AdaMLP fused persistent kernel (R15 = R14 + cudaFuncSetAttribute for the
// 48 KB dynamic smem request; R14's launch failed invalid-argument because
// dynamic 48 KB + static ~26 KB exceeded the default per-block limit).
//
// cp.async (LDGSTS) depth-3 weight pipeline in smem: weights stream
// DRAM->smem 2 tiles ahead; compute touches only smem (29-cyc LDS, hidden).
// Grid 256 x 256thr, launch_bounds(256,2), smem ~74KB/CTA -> 2 CTAs/SM,
// all 256 CTAs resident (148 SMs) -> grid barrier safe.
// CTA = (expert, quarter): phase1 quarter = 256-col rtile; phase2 = 256-r seg.
// Each weight element hits DRAM exactly once per phase.
// ============================================================================

typedef unsigned long long u64;

#define NEXP 64
#define NSLOT 1024
#define DIM 256
#define RDIM 1024
#define GRID 256
#define THREADS 256
#define TROWS 16                    // rows per weight tile
#define NTILES 16                   // 256 contraction rows / 16
#define WTILE (TROWS * 256)         // floats per tile (16 KB)
#define SSTRIDE 17                  // slot smem stride (conflict-free)
#define FULLMASK 0xFFFFFFFFu

__device__ float g_H[NSLOT * RDIM];          // 4 MB hidden (post-ReLU)
__device__ float g_P[4 * NSLOT * DIM];       // 4 MB partials (4 r-segments)
__device__ unsigned g_bar_cnt = 0;
__device__ unsigned g_bar_gen = 0;

__device__ __forceinline__ u64 pack2(float x, float y) {
    u64 r; asm("mov.b64 %0, {%1,%2};" : "=l"(r) : "f"(x), "f"(y)); return r;
}
__device__ __forceinline__ void fma2(u64& d, u64 a, u64 b) {
    asm("fma.rn.f32x2 %0, %1, %2, %0;" : "+l"(d) : "l"(a), "l"(b));
}
__device__ __forceinline__ float2 unpack2(u64 v) {
    float lo, hi; asm("mov.b64 {%0,%1}, %2;" : "=f"(lo), "=f"(hi) : "l"(v));
    return make_float2(lo, hi);
}
__device__ __forceinline__ void cp16(uint32_t dst_smem, const float* src) {
    asm volatile("cp.async.cg.shared.global [%0], [%1], 16;"
                 :: "r"(dst_smem), "l"(src) : "memory");
}
__device__ __forceinline__ void cp_commit() {
    asm volatile("cp.async.commit_group;" ::: "memory");
}
template <int N>
__device__ __forceinline__ void cp_wait() {
    asm volatile("cp.async.wait_group %0;" :: "n"(N) : "memory");
}

// Grid-wide barrier (release by all threads, acquire after spin).
__device__ __forceinline__ void grid_barrier() {
    __threadfence();
    __syncthreads();
    if (threadIdx.x == 0) {
        volatile unsigned* genp = &g_bar_gen;
        unsigned g = *genp;
        if (atomicAdd(&g_bar_cnt, 1u) == gridDim.x - 1) {
            g_bar_cnt = 0;
            __threadfence();
            atomicAdd(&g_bar_gen, 1u);
        } else {
            while (*genp == g) { __nanosleep(64); }
        }
        __threadfence();
    }
    __syncthreads();
}

__global__ __launch_bounds__(THREADS, 2) void fused_kernel(
    const float* __restrict__ slots,
    const float* __restrict__ w1,
    const float* __restrict__ b1,
    const float* __restrict__ w2,
    const float* __restrict__ b2,
    const int*   __restrict__ idx,
    float* __restrict__ out)
{
    extern __shared__ __align__(16) float wbuf[];        // 3 * WTILE = 48 KB dynamic
    __shared__ __align__(16) float sslot[256 * SSTRIDE]; // 17.4 KB: [d][slot]
    __shared__ int s_cnt[NEXP];
    __shared__ int s_base[NEXP];
    __shared__ int s_cur[NEXP];
    __shared__ int s_e[NSLOT];
    __shared__ int s_list[NSLOT];
    __shared__ int s_flag;

    const int tid = threadIdx.x;
    const int bid = blockIdx.x;
    const uint32_t wbuf_s = (uint32_t)__cvta_generic_to_shared(wbuf);

    // ------------- phase 0: DETERMINISTIC per-CTA grouping ------------------
    if (tid < NEXP) s_cnt[tid] = 0;
    if (tid == 0) s_flag = 0;
    __syncthreads();
    for (int t = tid; t < 512; t += THREADS)
        if (idx[2 * t + 1] != 0) s_flag = 1;    // int64 detect; benign race
    __syncthreads();
    const int flag = s_flag;
    for (int s = tid; s < NSLOT; s += THREADS) {
        int e = (flag ? idx[s] : idx[2 * s]) & (NEXP - 1);
        s_e[s] = e;
        atomicAdd(&s_cnt[e], 1);
    }
    __syncthreads();
    if (tid == 0) {
        int run = 0;
        for (int e = 0; e < NEXP; e++) { s_base[e] = run; run += s_cnt[e]; }
    }
    __syncthreads();
    if (tid < NEXP) s_cur[tid] = s_base[tid];
    __syncthreads();
    if (tid < 32) {                 // single-warp stable compaction
        const int lane = tid;
        for (int chunk = 0; chunk < 32; chunk++) {
            int s = chunk * 32 + lane;
            int e = s_e[s];
            unsigned mask = __match_any_sync(FULLMASK, e);
            int leader = __ffs(mask) - 1;
            int old = 0;
            if (lane == leader) old = atomicAdd(&s_cur[e], __popc(mask));
            old = __shfl_sync(FULLMASK, old, leader);
            int rank = __popc(mask & ((1u << lane) - 1u));
            s_list[old + rank] = s;
            __syncwarp();
        }
    }
    __syncthreads();

    const int e_blk = bid >> 2;              // 64 experts
    const int quad  = bid & 3;               // rtile (phase1) / rseg (phase2)
    const int grp   = tid >> 6;              // 4 slot-groups of 4
    const int c0    = (tid & 63) * 4;        // 4 output cols per thread
    const int n     = s_cnt[e_blk];
    const int base  = s_base[e_blk];

    // =============== phase 1: GEMM1  H = relu(slots @ w1 + b1) ==============
    {
        const float* Wb = w1 + (size_t)e_blk * (DIM * RDIM) + (size_t)quad * 256;
        const float4 bias = *(const float4*)(b1 + (size_t)e_blk * RDIM + quad * 256 + c0);

        for (int s0 = 0; s0 < n; s0 += 16) {
            const int scnt = min(16, n - s0);
            int sid[16];
#pragma unroll
            for (int j = 0; j < 16; j++)
                sid[j] = s_list[base + s0 + ((j < scnt) ? j : 0)];

            // launch weight pipeline (tiles 0,1) before slot fill
#pragma unroll
            for (int pt = 0; pt < 2; pt++) {
#pragma unroll
                for (int k = 0; k < 4; k++) {
                    int q = tid + k * THREADS;                    // 0..1023
                    cp16(wbuf_s + (uint32_t)((pt % 3) * WTILE + q * 4) * 4,
                         Wb + (size_t)(pt * TROWS + (q >> 6)) * RDIM + (q & 63) * 4);
                }
                cp_commit();
            }

            // slot tile fill: thread = d (0..255); 16 coalesced LDGs
            float sv[16];
#pragma unroll
            for (int j = 0; j < 16; j++)
                sv[j] = (j < scnt) ? slots[(size_t)sid[j] * DIM + tid] : 0.0f;
            __syncthreads();                       // prior readers done
#pragma unroll
            for (int j = 0; j < 16; j++) sslot[tid * SSTRIDE + j] = sv[j];
            __syncthreads();

            u64 acc[4][2];
#pragma unroll
            for (int p = 0; p < 4; p++) { acc[p][0] = 0ull; acc[p][1] = 0ull; }

            for (int t = 0; t < NTILES; t++) {
                if (t + 2 < NTILES) {
#pragma unroll
                    for (int k = 0; k < 4; k++) {
                        int q = tid + k * THREADS;
                        cp16(wbuf_s + (uint32_t)(((t + 2) % 3) * WTILE + q * 4) * 4,
                             Wb + (size_t)((t + 2) * TROWS + (q >> 6)) * RDIM + (q & 63) * 4);
                    }
                    cp_commit();
                }
                if (t < NTILES - 2) cp_wait<2>();
                else if (t == NTILES - 2) cp_wait<1>();
                else cp_wait<0>();
                __syncthreads();

                const float* wb = wbuf + (t % 3) * WTILE;
#pragma unroll
                for (int row = 0; row < TROWS; row++) {
                    float4 w4 = *(const float4*)(wb + row * 256 + c0);
                    const float* sr = sslot + (t * TROWS + row) * SSTRIDE + 4 * grp;
                    u64 s01 = pack2(sr[0], sr[1]);
                    u64 s23 = pack2(sr[2], sr[3]);
                    u64 wx = pack2(w4.x, w4.x);
                    u64 wy = pack2(w4.y, w4.y);
                    u64 wz = pack2(w4.z, w4.z);
                    u64 ww = pack2(w4.w, w4.w);
                    fma2(acc[0][0], s01, wx); fma2(acc[0][1], s23, wx);
                    fma2(acc[1][0], s01, wy); fma2(acc[1][1], s23, wy);
                    fma2(acc[2][0], s01, wz); fma2(acc[2][1], s23, wz);
                    fma2(acc[3][0], s01, ww); fma2(acc[3][1], s23, ww);
                }
                __syncthreads();                   // buffer reuse protection
            }

            // epilogue: this thread's 4 slots (group grp) x 4 cols
#pragma unroll
            for (int j = 0; j < 4; j++) {
                int jg = grp * 4 + j;
                if (jg < scnt) {
                    const int pr = j >> 1, hi = j & 1;
                    float2 a0 = unpack2(acc[0][pr]);
                    float2 a1 = unpack2(acc[1][pr]);
                    float2 a2 = unpack2(acc[2][pr]);
                    float2 a3 = unpack2(acc[3][pr]);
                    float4 o;
                    o.x = fmaxf((hi ? a0.y : a0.x) + bias.x, 0.0f);
                    o.y = fmaxf((hi ? a1.y : a1.x) + bias.y, 0.0f);
                    o.z = fmaxf((hi ? a2.y : a2.x) + bias.z, 0.0f);
                    o.w = fmaxf((hi ? a3.y : a3.x) + bias.w, 0.0f);
                    *(float4*)(g_H + (size_t)sid[jg] * RDIM + quad * 256 + c0) = o;
                }
            }
        }
    }

    grid_barrier();

    // =============== phase 2: GEMM2 partials  P[quad] = H_seg @ w2_seg ======
    {
        const int rbase = quad * 256;
        const float* Wb = w2 + (size_t)e_blk * (RDIM * DIM) + (size_t)rbase * DIM;
        float* Pp = g_P + (size_t)quad * (NSLOT * DIM);

        for (int s0 = 0; s0 < n; s0 += 16) {
            const int scnt = min(16, n - s0);
            int sid[16];
#pragma unroll
            for (int j = 0; j < 16; j++)
                sid[j] = s_list[base + s0 + ((j < scnt) ? j : 0)];

#pragma unroll
            for (int pt = 0; pt < 2; pt++) {
#pragma unroll
                for (int k = 0; k < 4; k++) {
                    int q = tid + k * THREADS;
                    cp16(wbuf_s + (uint32_t)((pt % 3) * WTILE + q * 4) * 4,
                         Wb + (size_t)(pt * TROWS + (q >> 6)) * DIM + (q & 63) * 4);
                }
                cp_commit();
            }

            float sv[16];
#pragma unroll
            for (int j = 0; j < 16; j++)
                sv[j] = (j < scnt) ? g_H[(size_t)sid[j] * RDIM + rbase + tid] : 0.0f;
            __syncthreads();
#pragma unroll
            for (int j = 0; j < 16; j++) sslot[tid * SSTRIDE + j] = sv[j];
            __syncthreads();

            u64 acc[4][2];
#pragma unroll
            for (int p = 0; p < 4; p++) { acc[p][0] = 0ull; acc[p][1] = 0ull; }

            for (int t = 0; t < NTILES; t++) {
                if (t + 2 < NTILES) {
#pragma unroll
                    for (int k = 0; k < 4; k++) {
                        int q = tid + k * THREADS;
                        cp16(wbuf_s + (uint32_t)(((t + 2) % 3) * WTILE + q * 4) * 4,
                             Wb + (size_t)((t + 2) * TROWS + (q >> 6)) * DIM + (q & 63) * 4);
                    }
                    cp_commit();
                }
                if (t < NTILES - 2) cp_wait<2>();
                else if (t == NTILES - 2) cp_wait<1>();
                else cp_wait<0>();
                __syncthreads();

                const float* wb = wbuf + (t % 3) * WTILE;
#pragma unroll
                for (int row = 0; row < TROWS; row++) {
                    float4 w4 = *(const float4*)(wb + row * 256 + c0);
                    const float* sr = sslot + (t * TROWS + row) * SSTRIDE + 4 * grp;
                    u64 s01 = pack2(sr[0], sr[1]);
                    u64 s23 = pack2(sr[2], sr[3]);
                    u64 wx = pack2(w4.x, w4.x);
                    u64 wy = pack2(w4.y, w4.y);
                    u64 wz = pack2(w4.z, w4.z);
                    u64 ww = pack2(w4.w, w4.w);
                    fma2(acc[0][0], s01, wx); fma2(acc[0][1], s23, wx);
                    fma2(acc[1][0], s01, wy); fma2(acc[1][1], s23, wy);
                    fma2(acc[2][0], s01, wz); fma2(acc[2][1], s23, wz);
                    fma2(acc[3][0], s01, ww); fma2(acc[3][1], s23, ww);
                }
                __syncthreads();
            }

#pragma unroll
            for (int j = 0; j < 4; j++) {
                int jg = grp * 4 + j;
                if (jg < scnt) {
                    const int pr = j >> 1, hi = j & 1;
                    float2 a0 = unpack2(acc[0][pr]);
                    float2 a1 = unpack2(acc[1][pr]);
                    float2 a2 = unpack2(acc[2][pr]);
                    float2 a3 = unpack2(acc[3][pr]);
                    float4 o;
                    o.x = hi ? a0.y : a0.x;
                    o.y = hi ? a1.y : a1.x;
                    o.z = hi ? a2.y : a2.x;
                    o.w = hi ? a3.y : a3.x;
                    *(float4*)(Pp + (size_t)sid[jg] * DIM + c0) = o;
                }
            }
        }
    }

    grid_barrier();

    // =============== phase 3: reduce partials + b2 -> out (float4) ==========
    {
        int t = bid * THREADS + tid;             // float4 index; 65536 total
        int slot = t >> 6;
        int e = s_e[slot];
        const float4* P4 = (const float4*)g_P;
        const int SEG = NSLOT * DIM / 4;
        float4 v0 = P4[t];
        float4 v1 = P4[SEG + t];
        float4 v2 = P4[2 * SEG + t];
        float4 v3 = P4[3 * SEG + t];
        float4 bb = ((const float4*)b2)[e * 64 + (t & 63)];
        float4 r;
        r.x = v0.x + v1.x + v2.x + v3.x + bb.x;
        r.y = v0.y + v1.y + v2.y + v3.y + bb.y;
        r.z = v0.z + v1.z + v2.z + v3.z + bb.z;
        r.w = v0.w + v1.w + v2.w + v3.w + bb.w;
        ((float4*)out)[t] = r;
    }
}

// ----------------------------------------------------------------------------
extern "C" void kernel_launch(void* const* d_in, const int* in_sizes, int n_in,
                              void* d_out, int out_size)
{
    const float* slots = (const float*)d_in[0];
    const float* w1    = (const float*)d_in[1];
    const float* b1    = (const float*)d_in[2];
    const float* w2    = (const float*)d_in[3];
    const float* b2    = (const float*)d_in[4];
    const int*   idx   = (const int*)d_in[5];
    float* out = (float*)d_out;

    // Raise the dynamic smem cap (48 KB dynamic + ~26 KB static per CTA).
    // Host attribute set, not a stream op -> legal under graph capture;
    // idempotent and deterministic.
    cudaFuncSetAttribute(fused_kernel,
                         cudaFuncAttributeMaxDynamicSharedMemorySize,
                         3 * WTILE * sizeof(float));

    fused_kernel<<<GRID, THREADS, 3 * WTILE * sizeof(float)>>>(
        slots, w1, b1, w2, b2, idx, out);
}

// round 17
// speedup vs baseline: 1.3263x; 1.3263x over previous
#include <cuda_runtime.h>
#include <cstdint>

// ============================================================================
// AdaMLP fused persistent kernel (R16 = R13 + register triple-buffered weight
// pipeline). 1024 slots, 64 experts, 256 -> 1024(relu) -> 256, fp32 (FFMA2).
//
// Diagnosis synthesis: R5/R11 were LSU-dispatch bound (24 LSU ops / 32
// warp-FFMA2 x 4cyc floor ~= 94us, warp-count independent). R13 fixed LSU
// economy (2 LSU / 8 FFMA2) but was DRAM-latency bound (weights front-batched
// 4 rows, consumed immediately, MLP~4, issue 15%). R15's cp.async fixed
// latency but added CTA-wide barriers + LDGSTS rt=8 (106us).
// R16: keep R13's economy; weights flow through a 3-deep ring of 4-row
// register windows (LDG.128), consumed 2 windows behind issue -> ~600cyc
// grace, no barriers, no cp.async. Manual 3-window rotation keeps buffer
// indices static (registers, not local mem).
// ============================================================================

typedef unsigned long long u64;

#define NEXP 64
#define NSLOT 1024
#define DIM 256
#define RDIM 1024
#define GRID 512
#define FULLMASK 0xFFFFFFFFu

__device__ float g_H[NSLOT * RDIM];          // 4 MB hidden (post-ReLU)
__device__ float g_P[4 * NSLOT * DIM];       // 4 MB partials (4 r-segments)
__device__ unsigned g_bar_cnt = 0;
__device__ unsigned g_bar_gen = 0;

__device__ __forceinline__ u64 pack2(float x, float y) {
    u64 r; asm("mov.b64 %0, {%1,%2};" : "=l"(r) : "f"(x), "f"(y)); return r;
}
__device__ __forceinline__ void fma2(u64& d, u64 a, u64 b) {
    asm("fma.rn.f32x2 %0, %1, %2, %0;" : "+l"(d) : "l"(a), "l"(b));
}
__device__ __forceinline__ float2 unpack2(u64 v) {
    float lo, hi; asm("mov.b64 {%0,%1}, %2;" : "=f"(lo), "=f"(hi) : "l"(v));
    return make_float2(lo, hi);
}

// Grid-wide barrier (release by all threads, acquire after spin).
__device__ __forceinline__ void grid_barrier() {
    __threadfence();
    __syncthreads();
    if (threadIdx.x == 0) {
        volatile unsigned* genp = &g_bar_gen;
        unsigned g = *genp;
        if (atomicAdd(&g_bar_cnt, 1u) == gridDim.x - 1) {
            g_bar_cnt = 0;
            __threadfence();
            atomicAdd(&g_bar_gen, 1u);
        } else {
            while (*genp == g) { __nanosleep(64); }
        }
        __threadfence();
    }
    __syncthreads();
}

// One 4-row compute window: 4x (1 LDS.128 broadcast + 4 packs + 8 FFMA2).
// sp already offset for the phase; stride = ull2 elements per row.
template <int STRIDE>
__device__ __forceinline__ void win_compute(
    u64 acc[4][2], const float4 w[4], const ulonglong2* sp, int row0)
{
#pragma unroll
    for (int i = 0; i < 4; i++) {
        float4 w4 = w[i];
        ulonglong2 s = sp[(size_t)(row0 + i) * STRIDE];
        u64 w0 = pack2(w4.x, w4.x);
        u64 w1 = pack2(w4.y, w4.y);
        u64 w2 = pack2(w4.z, w4.z);
        u64 w3 = pack2(w4.w, w4.w);
        fma2(acc[0][0], s.x, w0); fma2(acc[0][1], s.y, w0);
        fma2(acc[1][0], s.x, w1); fma2(acc[1][1], s.y, w1);
        fma2(acc[2][0], s.x, w2); fma2(acc[2][1], s.y, w2);
        fma2(acc[3][0], s.x, w3); fma2(acc[3][1], s.y, w3);
    }
}

// Load one 4-row window of weights (4 x LDG.128), row-major stride WS floats.
template <int WS>
__device__ __forceinline__ void win_load(float4 w[4], const float* Wp, int row0)
{
#pragma unroll
    for (int i = 0; i < 4; i++)
        w[i] = *(const float4*)(Wp + (size_t)(row0 + i) * WS);
}

// Full 256-row (64-window) triple-buffered mainloop.
// WS = weight row stride (floats); STRIDE = slot-smem ull2 row stride.
template <int WS, int STRIDE>
__device__ __forceinline__ void mainloop_256(
    u64 acc[4][2], const float* Wp, const ulonglong2* sp)
{
    float4 wb0[4], wb1[4], wb2[4];
    win_load<WS>(wb0, Wp, 0);        // window 0
    win_load<WS>(wb1, Wp, 4);        // window 1
    // 64 windows = 21 triples (0..62) + tail window 63.
    for (int k = 0; k < 21; k++) {
        int t0 = 3 * k;              // windows t0, t0+1, t0+2 (<= 62)
        win_load<WS>(wb2, Wp, (t0 + 2) * 4);
        win_compute<STRIDE>(acc, wb0, sp, t0 * 4);
        win_load<WS>(wb0, Wp, (t0 + 3) * 4);            // t0+3 <= 63 ok
        win_compute<STRIDE>(acc, wb1, sp, (t0 + 1) * 4);
        if (t0 + 4 < 64) win_load<WS>(wb1, Wp, (t0 + 4) * 4);
        win_compute<STRIDE>(acc, wb2, sp, (t0 + 2) * 4);
    }
    win_compute<STRIDE>(acc, wb0, sp, 63 * 4);          // tail window 63
}

__global__ __launch_bounds__(128, 4) void fused_kernel(
    const float* __restrict__ slots,
    const float* __restrict__ w1,
    const float* __restrict__ b1,
    const float* __restrict__ w2,
    const float* __restrict__ b2,
    const int*   __restrict__ idx,
    float* __restrict__ out)
{
    __shared__ int s_cnt[NEXP];
    __shared__ int s_base[NEXP];
    __shared__ int s_cur[NEXP];
    __shared__ int s_e[NSLOT];
    __shared__ int s_list[NSLOT];
    __shared__ __align__(16) float sbuf[2048];   // 8 KB (phase2); phase1 4 KB
    __shared__ int s_flag;

    const int tid = threadIdx.x;
    const int bid = blockIdx.x;

    // ------------- phase 0: DETERMINISTIC per-CTA grouping ------------------
    if (tid < NEXP) s_cnt[tid] = 0;
    if (tid == 0) s_flag = 0;
    __syncthreads();
    for (int t = tid; t < 512; t += 128)
        if (idx[2 * t + 1] != 0) s_flag = 1;    // int64 detect; benign race
    __syncthreads();
    const int flag = s_flag;
    for (int s = tid; s < NSLOT; s += 128) {
        int e = (flag ? idx[s] : idx[2 * s]) & (NEXP - 1);
        s_e[s] = e;
        atomicAdd(&s_cnt[e], 1);
    }
    __syncthreads();
    if (tid == 0) {
        int run = 0;
        for (int e = 0; e < NEXP; e++) { s_base[e] = run; run += s_cnt[e]; }
    }
    __syncthreads();
    if (tid < NEXP) s_cur[tid] = s_base[tid];
    __syncthreads();
    if (tid < 32) {                 // single-warp stable compaction
        const int lane = tid;
        for (int chunk = 0; chunk < 32; chunk++) {
            int s = chunk * 32 + lane;
            int e = s_e[s];
            unsigned mask = __match_any_sync(FULLMASK, e);
            int leader = __ffs(mask) - 1;
            int old = 0;
            if (lane == leader) old = atomicAdd(&s_cur[e], __popc(mask));
            old = __shfl_sync(FULLMASK, old, leader);
            int rank = __popc(mask & ((1u << lane) - 1u));
            s_list[old + rank] = s;
            __syncwarp();
        }
    }
    __syncthreads();

    const int e_blk = bid >> 3;      // 64 experts
    const int sub   = bid & 7;

    // ---------------- phase 1: GEMM1 (H = relu(slots @ w1 + b1)) ------------
    // sub -> rtile (2 tiles of 512 cols) x zq (4 slot-quarters, SC=4).
    {
        const int rtile = sub & 1;
        const int zq    = sub >> 1;
        const int n = s_cnt[e_blk], base = s_base[e_blk];
        const int c0 = rtile * 512 + tid * 4;
        const float* Wp = w1 + (size_t)e_blk * (DIM * RDIM) + c0;
        const float4 bias = *(const float4*)(b1 + (size_t)e_blk * RDIM + c0);

        for (int s0 = zq * 4; s0 < n; s0 += 16) {
            const int sc = min(4, n - s0);
            int sid[4];
#pragma unroll
            for (int j = 0; j < 4; j++)
                sid[j] = s_list[base + s0 + ((j < sc) ? j : 0)];

            // fill sbuf[d*4 + j] (4 slots x 256 d, 4 KB), batched LDGs
            const int jf = tid & 3;
            const int d0 = tid >> 2;
            const int fvalid = (jf < sc);
            float v[8];
#pragma unroll
            for (int i = 0; i < 8; i++) {
                int d = d0 + 32 * i;
                v[i] = fvalid ? slots[(size_t)sid[jf] * DIM + d] : 0.0f;
            }
            __syncthreads();                 // prev-chunk readers done
#pragma unroll
            for (int i = 0; i < 8; i++) sbuf[tid + 128 * i] = v[i];
            __syncthreads();

            u64 acc[4][2];
#pragma unroll
            for (int p = 0; p < 4; p++) { acc[p][0] = 0ull; acc[p][1] = 0ull; }

            mainloop_256<RDIM, 1>(acc, Wp, (const ulonglong2*)sbuf);

#pragma unroll
            for (int j = 0; j < 4; j++) {
                if (j < sc) {
                    const int pr = j >> 1, hi = j & 1;
                    float2 a0 = unpack2(acc[0][pr]);
                    float2 a1 = unpack2(acc[1][pr]);
                    float2 a2 = unpack2(acc[2][pr]);
                    float2 a3 = unpack2(acc[3][pr]);
                    float4 o;
                    o.x = fmaxf((hi ? a0.y : a0.x) + bias.x, 0.0f);
                    o.y = fmaxf((hi ? a1.y : a1.x) + bias.y, 0.0f);
                    o.z = fmaxf((hi ? a2.y : a2.x) + bias.z, 0.0f);
                    o.w = fmaxf((hi ? a3.y : a3.x) + bias.w, 0.0f);
                    *(float4*)(g_H + (size_t)sid[j] * RDIM + c0) = o;
                }
            }
        }
    }

    grid_barrier();

    // ---------------- phase 2: GEMM2 partials (P[seg] = H_seg @ w2_seg) -----
    // sub -> rseg (4 segments of 256 r) x zh (2 slot-halves, SC=8).
    // 128 thr = 2 groups of 64; group g handles slots jg = g*4 + 0..3.
    {
        const int rseg = sub & 3;
        const int zh   = sub >> 2;
        const int rbase = rseg * 256;
        const int grp = tid >> 6;
        const int c0  = (tid & 63) * 4;
        const int n = s_cnt[e_blk], base = s_base[e_blk];
        const float* Wp = w2 + (size_t)e_blk * (RDIM * DIM) + (size_t)rbase * DIM + c0;
        float* Pp = g_P + (size_t)rseg * (NSLOT * DIM);

        for (int s0 = zh * 8; s0 < n; s0 += 16) {
            const int sc = min(8, n - s0);
            int sid[4];
#pragma unroll
            for (int j = 0; j < 4; j++) {
                int jg = grp * 4 + j;
                sid[j] = s_list[base + s0 + ((jg < sc) ? jg : 0)];
            }

            // fill sbuf[r*8 + g*4 + j] (8 slots x 256 r, 8 KB), batched LDGs
            const int jf = tid & 3;
            const int gf = (tid >> 2) & 1;
            const int r0 = tid >> 3;
            const int jgf = gf * 4 + jf;
            const int fvalid = (jgf < sc);
            const int sidf = s_list[base + s0 + (fvalid ? jgf : 0)];
            float v[16];
#pragma unroll
            for (int i = 0; i < 16; i++) {
                int r = r0 + 16 * i;
                v[i] = fvalid ? g_H[(size_t)sidf * RDIM + rbase + r] : 0.0f;
            }
            __syncthreads();
#pragma unroll
            for (int i = 0; i < 16; i++) sbuf[tid + 128 * i] = v[i];
            __syncthreads();

            u64 acc[4][2];
#pragma unroll
            for (int p = 0; p < 4; p++) { acc[p][0] = 0ull; acc[p][1] = 0ull; }

            mainloop_256<DIM, 2>(acc, Wp, (const ulonglong2*)sbuf + grp);

#pragma unroll
            for (int j = 0; j < 4; j++) {
                int jg = grp * 4 + j;
                if (jg < sc) {
                    const int pr = j >> 1, hi = j & 1;
                    float2 a0 = unpack2(acc[0][pr]);
                    float2 a1 = unpack2(acc[1][pr]);
                    float2 a2 = unpack2(acc[2][pr]);
                    float2 a3 = unpack2(acc[3][pr]);
                    float4 o;
                    o.x = hi ? a0.y : a0.x;
                    o.y = hi ? a1.y : a1.x;
                    o.z = hi ? a2.y : a2.x;
                    o.w = hi ? a3.y : a3.x;
                    *(float4*)(Pp + (size_t)sid[j] * DIM + c0) = o;
                }
            }
        }
    }

    grid_barrier();

    // ---------------- phase 3: reduce partials + b2 -> out (float4) ---------
    {
        int t = bid * 128 + tid;                 // float4 index; 65536 total
        int slot = t >> 6;
        int e = s_e[slot];
        const float4* P4 = (const float4*)g_P;
        const int SEG = NSLOT * DIM / 4;
        float4 v0 = P4[t];
        float4 v1 = P4[SEG + t];
        float4 v2 = P4[2 * SEG + t];
        float4 v3 = P4[3 * SEG + t];
        float4 bb = ((const float4*)b2)[e * 64 + (t & 63)];
        float4 r;
        r.x = v0.x + v1.x + v2.x + v3.x + bb.x;
        r.y = v0.y + v1.y + v2.y + v3.y + bb.y;
        r.z = v0.z + v1.z + v2.z + v3.z + bb.z;
        r.w = v0.w + v1.w + v2.w + v3.w + bb.w;
        ((float4*)out)[t] = r;
    }
}

// ----------------------------------------------------------------------------
extern "C" void kernel_launch(void* const* d_in, const int* in_sizes, int n_in,
                              void* d_out, int out_size)
{
    const float* slots = (const float*)d_in[0];
    const float* w1    = (const float*)d_in[1];
    const float* b1    = (const float*)d_in[2];
    const float* w2    = (const float*)d_in[3];
    const float* b2    = (const float*)d_in[4];
    const int*   idx   = (const int*)d_in[5];
    float* out = (float*)d_out;

    fused_kernel<<<GRID, 128>>>(slots, w1, b1, w2, b2, idx, out);
}